// round 6
// baseline (speedup 1.0000x reference)
#include <cuda_runtime.h>
#include <cuda_bf16.h>

#define HW      589824      // 768*768
#define NG      147456      // HW/4 int4-groups per batch
#define BPB     222         // blocks per batch
#define TPB     128
#define NB      8
#define NC      9
#define NOUT    90          // 9 classes * (9 channels + count)

__device__ float g_part[NB * BPB * NOUT];
__device__ float g_tot[NB * NOUT];
__device__ int   g_bcnt[NB];
__device__ int   g_fcnt;

// one setp + 5 guarded packed-f32x2 adds for class c
#define ACC_CLASS(c)                                                          \
    asm("{\n\t.reg .pred p;\n\t"                                              \
        "setp.eq.s32 p, %10, " #c ";\n\t"                                     \
        "@p add.rn.f32x2 %0, %0, %5;\n\t"                                     \
        "@p add.rn.f32x2 %1, %1, %6;\n\t"                                     \
        "@p add.rn.f32x2 %2, %2, %7;\n\t"                                     \
        "@p add.rn.f32x2 %3, %3, %8;\n\t"                                     \
        "@p add.rn.f32x2 %4, %4, %9;\n\t}"                                    \
        : "+l"(acc[(c)*5+0]), "+l"(acc[(c)*5+1]), "+l"(acc[(c)*5+2]),         \
          "+l"(acc[(c)*5+3]), "+l"(acc[(c)*5+4])                              \
        : "l"(pk0), "l"(pk1), "l"(pk2), "l"(pk3), "l"(pk4), "r"(m))

__device__ __forceinline__ unsigned long long packf2(float a, float b) {
    unsigned long long r;
    asm("mov.b64 %0, {%1, %2};" : "=l"(r) : "f"(a), "f"(b));
    return r;
}

__global__ void __launch_bounds__(TPB) fused_kernel(
    const int* __restrict__ masks, const float* __restrict__ outs,
    float* __restrict__ out)
{
    __shared__ float s_red[4][NOUT];
    __shared__ int s_last;
    __shared__ float per[64], pres[64];

    const int tid  = threadIdx.x;
    const int lane = tid & 31;
    const int w    = tid >> 5;
    const int b    = blockIdx.y;
    const int blk  = blockIdx.x;

    // 45 packed f32x2 accumulators: [class][pair]; pair4 = (ch8, count)
    unsigned long long acc[45];
    #pragma unroll
    for (int i = 0; i < 45; i++) acc[i] = 0ull;

    const int4*   m4 = (const int4*)(masks + (size_t)b * HW);
    const float4* o4 = (const float4*)(outs + (size_t)b * NC * HW);

    #pragma unroll 1
    for (int g = blk * TPB + tid; g < NG; g += BPB * TPB) {
        int4 mm = m4[g];
        float4 v[NC];
        #pragma unroll
        for (int c = 0; c < NC; c++) v[c] = o4[(size_t)c * NG + g];

        #pragma unroll
        for (int j = 0; j < 4; j++) {
            int m = (j == 0) ? mm.x : (j == 1) ? mm.y : (j == 2) ? mm.z : mm.w;
            float e[NC];
            #pragma unroll
            for (int c = 0; c < NC; c++)
                e[c] = (j == 0) ? v[c].x : (j == 1) ? v[c].y : (j == 2) ? v[c].z : v[c].w;
            unsigned long long pk0 = packf2(e[0], e[1]);
            unsigned long long pk1 = packf2(e[2], e[3]);
            unsigned long long pk2 = packf2(e[4], e[5]);
            unsigned long long pk3 = packf2(e[6], e[7]);
            unsigned long long pk4 = packf2(e[8], 1.0f);
            ACC_CLASS(0); ACC_CLASS(1); ACC_CLASS(2);
            ACC_CLASS(3); ACC_CLASS(4); ACC_CLASS(5);
            ACC_CLASS(6); ACC_CLASS(7); ACC_CLASS(8);
        }
    }

    // warp butterfly on packed accumulators
    #pragma unroll
    for (int off = 16; off > 0; off >>= 1) {
        #pragma unroll
        for (int i = 0; i < 45; i++) {
            unsigned long long o = __shfl_xor_sync(0xFFFFFFFFu, acc[i], off);
            asm("add.rn.f32x2 %0, %0, %1;" : "+l"(acc[i]) : "l"(o));
        }
    }
    if (lane == 0) {
        #pragma unroll
        for (int i = 0; i < 45; i++) {
            int c = i / 5, p = i % 5;
            float lo, hi;
            asm("mov.b64 {%0, %1}, %2;" : "=f"(lo), "=f"(hi) : "l"(acc[i]));
            s_red[w][c * 10 + 2 * p]     = lo;
            s_red[w][c * 10 + 2 * p + 1] = hi;
        }
    }
    __syncthreads();
    if (tid < NOUT) {
        float s = s_red[0][tid] + s_red[1][tid] + s_red[2][tid] + s_red[3][tid];
        g_part[((size_t)(b * BPB + blk)) * NOUT + tid] = s;
    }
    __threadfence();
    __syncthreads();
    if (tid == 0) s_last = (atomicAdd(&g_bcnt[b], 1) == BPB - 1);
    __syncthreads();
    if (!s_last) return;

    // ── per-batch reducer (8 in parallel, one per batch) ──
    __threadfence();
    if (tid < NOUT) {
        float s = 0.0f;
        #pragma unroll 6
        for (int k = 0; k < BPB; k++)
            s += g_part[((size_t)(b * BPB + k)) * NOUT + tid];
        g_tot[b * NOUT + tid] = s;
    }
    __threadfence();
    __syncthreads();
    if (tid == 0) s_last = (atomicAdd(&g_fcnt, 1) == NB - 1);
    __syncthreads();
    if (!s_last) return;

    // ── global final block: log-softmax loss over 64 protos ──
    __threadfence();
    if (tid < 64) {
        int bb = tid / 8, k = tid % 8 + 1;          // classes 1..8
        float cnt   = g_tot[bb * NOUT + k * 10 + 9];
        float denom = fmaxf(cnt, 1.0f);
        float p[NC], mx = -1e30f;
        #pragma unroll
        for (int c = 0; c < NC; c++) {
            p[c] = g_tot[bb * NOUT + k * 10 + c] / denom;
            mx = fmaxf(mx, p[c]);
        }
        float se = 0.0f;
        #pragma unroll
        for (int c = 0; c < NC; c++) se += expf(p[c] - mx);
        float lse = mx + logf(se);
        float l = 0.0f;
        #pragma unroll
        for (int c = 0; c < NC; c++) {
            float tgt = (c == k) ? 0.9f : 0.0125f;
            l += tgt * (p[c] - lse);
        }
        bool present = cnt > 0.0f;
        per[tid]  = present ? -l   : 0.0f;
        pres[tid] = present ? 1.0f : 0.0f;
    }
    __syncthreads();
    if (tid == 0) {
        float L = 0.0f, P = 0.0f;
        #pragma unroll
        for (int i = 0; i < 64; i++) { L += per[i]; P += pres[i]; }
        out[0] = L / fmaxf(P, 1.0f);
        g_fcnt = 0;
    }
    if (tid < NB) g_bcnt[tid] = 0;
}

extern "C" void kernel_launch(void* const* d_in, const int* in_sizes, int n_in,
                              void* d_out, int out_size)
{
    const int* masks;
    const float* outs;
    if (in_sizes[0] == NB * HW) {
        masks = (const int*)d_in[0];
        outs  = (const float*)d_in[1];
    } else {
        masks = (const int*)d_in[1];
        outs  = (const float*)d_in[0];
    }
    float* out = (float*)d_out;

    dim3 grid(BPB, NB);
    fused_kernel<<<grid, TPB>>>(masks, outs, out);
}

// round 12
// speedup vs baseline: 1.5497x; 1.5497x over previous
#include <cuda_runtime.h>
#include <cuda_bf16.h>

#define HW      589824      // 768*768
#define NG      147456      // HW/4 int4-groups per batch
#define BPB     72          // blocks per batch -> ITERS exact
#define TPB     128
#define ITERS   16          // NG / (BPB*TPB)
#define NB      8
#define NC      9
#define NPACK   5           // 10 values (9 ch + count) as float2
#define NOUT    90

__device__ float g_part[NB * BPB * NOUT];
__device__ float g_tot[NB * NOUT];
__device__ int   g_bcnt[NB];
__device__ int   g_fcnt;

__global__ void __launch_bounds__(TPB, 4) fused_kernel(
    const int* __restrict__ masks, const float* __restrict__ outs,
    float* __restrict__ out)
{
    // per-lane-private accumulators: [warp][class][pack][lane], lane innermost
    __shared__ float2 sh[4 * NC * NPACK * 32];   // 46080 B
    __shared__ int s_last;
    __shared__ float per[64], pres[64];

    const int tid  = threadIdx.x;
    const int lane = tid & 31;
    const int w    = tid >> 5;
    const int b    = blockIdx.y;
    const int blk  = blockIdx.x;

    // lane-private zero (no barrier needed before use)
    #pragma unroll
    for (int m = 0; m < NC; m++)
        #pragma unroll
        for (int p = 0; p < NPACK; p++)
            sh[((w * NC + m) * NPACK + p) * 32 + lane] = make_float2(0.f, 0.f);

    const int4*   m4 = (const int4*)(masks + (size_t)b * HW);
    const float4* o4 = (const float4*)(outs + (size_t)b * NC * HW);
    const int stride = BPB * TPB;

    int g = blk * TPB + tid;
    int4   mmA = m4[g];
    float4 vA[NC];
    #pragma unroll
    for (int c = 0; c < NC; c++) vA[c] = o4[(size_t)c * NG + g];

    #pragma unroll 2
    for (int it = 0; it < ITERS; it++) {
        int4   mmB;
        float4 vB[NC];
        if (it + 1 < ITERS) {                 // prefetch next tile
            int gn = g + stride;
            mmB = m4[gn];
            #pragma unroll
            for (int c = 0; c < NC; c++) vB[c] = o4[(size_t)c * NG + gn];
        }

        #pragma unroll
        for (int j = 0; j < 4; j++) {
            int m = (j == 0) ? mmA.x : (j == 1) ? mmA.y : (j == 2) ? mmA.z : mmA.w;
            float2* base = sh + ((w * NC + m) * NPACK) * 32 + lane;

            float pv[10];
            #pragma unroll
            for (int c = 0; c < NC; c++)
                pv[c] = (j == 0) ? vA[c].x : (j == 1) ? vA[c].y
                      : (j == 2) ? vA[c].z : vA[c].w;
            pv[9] = 1.0f;                     // count channel

            #pragma unroll
            for (int p = 0; p < NPACK; p++) {
                float2 a = base[p * 32];
                a.x += pv[2 * p];
                a.y += pv[2 * p + 1];
                base[p * 32] = a;
            }
        }

        mmA = mmB;
        #pragma unroll
        for (int c = 0; c < NC; c++) vA[c] = vB[c];
        g += stride;
    }
    __syncthreads();

    // fold warp regions 1..3 into warp 0's region (all 128 threads)
    for (int i = tid; i < NC * NPACK * 32; i += TPB) {
        float2 a = sh[i];
        float2 x = sh[i + 1440], y = sh[i + 2880], z = sh[i + 4320];
        a.x += x.x + y.x + z.x;
        a.y += x.y + y.y + z.y;
        sh[i] = a;
    }
    __syncthreads();

    // 32-lane sums -> 90 partials for this block
    if (tid < NOUT) {
        int m = tid / 10, cc = tid % 10, p = cc >> 1, hf = cc & 1;
        float s = 0.0f;
        #pragma unroll 8
        for (int l = 0; l < 32; l++) {
            float2 a = sh[(m * NPACK + p) * 32 + l];
            s += hf ? a.y : a.x;
        }
        g_part[((size_t)(b * BPB + blk)) * NOUT + tid] = s;
    }
    __threadfence();
    __syncthreads();
    if (tid == 0) s_last = (atomicAdd(&g_bcnt[b], 1) == BPB - 1);
    __syncthreads();
    if (!s_last) return;

    // ── per-batch reducer (8 in parallel, one per batch) ──
    __threadfence();
    if (tid < NOUT) {
        float s = 0.0f;
        #pragma unroll 6
        for (int k = 0; k < BPB; k++)
            s += g_part[((size_t)(b * BPB + k)) * NOUT + tid];
        g_tot[b * NOUT + tid] = s;
    }
    __threadfence();
    __syncthreads();
    if (tid == 0) s_last = (atomicAdd(&g_fcnt, 1) == NB - 1);
    __syncthreads();
    if (!s_last) return;

    // ── global final block: log-softmax loss over 64 protos ──
    __threadfence();
    if (tid < 64) {
        int bb = tid / 8, k = tid % 8 + 1;          // classes 1..8
        float cnt   = g_tot[bb * NOUT + k * 10 + 9];
        float denom = fmaxf(cnt, 1.0f);
        float p[NC], mx = -1e30f;
        #pragma unroll
        for (int c = 0; c < NC; c++) {
            p[c] = g_tot[bb * NOUT + k * 10 + c] / denom;
            mx = fmaxf(mx, p[c]);
        }
        float se = 0.0f;
        #pragma unroll
        for (int c = 0; c < NC; c++) se += expf(p[c] - mx);
        float lse = mx + logf(se);
        float l = 0.0f;
        #pragma unroll
        for (int c = 0; c < NC; c++) {
            float tgt = (c == k) ? 0.9f : 0.0125f;
            l += tgt * (p[c] - lse);
        }
        bool present = cnt > 0.0f;
        per[tid]  = present ? -l   : 0.0f;
        pres[tid] = present ? 1.0f : 0.0f;
    }
    __syncthreads();
    if (tid == 0) {
        float L = 0.0f, P = 0.0f;
        #pragma unroll
        for (int i = 0; i < 64; i++) { L += per[i]; P += pres[i]; }
        out[0] = L / fmaxf(P, 1.0f);
        g_fcnt = 0;
    }
    if (tid < NB) g_bcnt[tid] = 0;
}

extern "C" void kernel_launch(void* const* d_in, const int* in_sizes, int n_in,
                              void* d_out, int out_size)
{
    const int* masks;
    const float* outs;
    if (in_sizes[0] == NB * HW) {
        masks = (const int*)d_in[0];
        outs  = (const float*)d_in[1];
    } else {
        masks = (const int*)d_in[1];
        outs  = (const float*)d_in[0];
    }
    float* out = (float*)d_out;

    static bool configured = false;
    if (!configured) {
        cudaFuncSetAttribute(fused_kernel,
                             cudaFuncAttributePreferredSharedMemoryCarveout, 100);
        configured = true;
    }

    dim3 grid(BPB, NB);
    fused_kernel<<<grid, TPB>>>(masks, outs, out);
}